// round 9
// baseline (speedup 1.0000x reference)
#include <cuda_runtime.h>
#include <cstddef>
#include <cstdint>

#define BB 4
#define TT 4096
#define DD 1024
#define NN 64
#define RR 16
#define KK 4
#define BT (BB * TT)
#define SG 32    // scan prefetch group size

// Scratch (device globals — no allocation allowed)
__device__ float2 g_dp[BT * NN + SG * NN];    // interleaved {delta, proj}; padded tail
__device__ float g_states[BT * NN];

// ---------------------------------------------------------------------------
// tf32 helpers (fragment layout verified in round 8)
// ---------------------------------------------------------------------------
__device__ __forceinline__ uint32_t tf32_hi(float x) {
    uint32_t r;
    asm("cvt.rna.tf32.f32 %0, %1;" : "=r"(r) : "f"(x));
    return r;
}
__device__ __forceinline__ void mma_tf32(float4& d,
                                         uint32_t a0, uint32_t a1, uint32_t a2, uint32_t a3,
                                         uint32_t b0, uint32_t b1) {
    asm("mma.sync.aligned.m16n8k8.row.col.f32.tf32.tf32.f32 "
        "{%0,%1,%2,%3}, {%4,%5,%6,%7}, {%8,%9}, {%0,%1,%2,%3};"
        : "+f"(d.x), "+f"(d.y), "+f"(d.z), "+f"(d.w)
        : "r"(a0), "r"(a1), "r"(a2), "r"(a3), "r"(b0), "r"(b1));
}
// 3-pass split-tf32: D += alo*bhi + ahi*blo + ahi*bhi
#define MMA3(ACC, AH, AL, BH, BL)                                          \
    do {                                                                   \
        mma_tf32(ACC, AL[0], AL[1], AL[2], AL[3], BH[0], BH[1]);           \
        mma_tf32(ACC, AH[0], AH[1], AH[2], AH[3], BL[0], BL[1]);           \
        mma_tf32(ACC, AH[0], AH[1], AH[2], AH[3], BH[0], BH[1]);           \
    } while (0)

// ---------------------------------------------------------------------------
// Stage 1 (fused): per 128-row tile, full K=1024, split-tf32 MMA.
//   proj  = (x + causal_conv(x)) @ in_w^T + in_b      (cols 0..63)
//   delta = tanh(x @ dt_w^T + dt_b) @ tr_w^T          (via dt cols 64..79)
// Writes interleaved g_dp directly. grid 128, block 256 (8 warps).
// Warp tile: 32 rows (2 x m16) x 40 cols (5 x n8). dt cols use A = x.
// ---------------------------------------------------------------------------
#define XP2 36    // [row][k] smem pitch
#define NROW 131  // 128 rows + 3 halo (idx 128..130 = t0-3..t0-1)

__global__ __launch_bounds__(256) void stage1_kernel(
    const float* __restrict__ x,
    const float* __restrict__ conv_w,
    const float* __restrict__ in_w,
    const float* __restrict__ in_b,
    const float* __restrict__ dt_w,
    const float* __restrict__ dt_b,
    const float* __restrict__ tr_w)
{
    extern __shared__ float s1[];
    float* xsf = s1;                      // [131][36] fp32 x chunk
    float* ash = xsf + NROW * XP2;        // [128][36] tf32-hi of (x+conv)
    float* asl = ash + 128 * XP2;         // [128][36] tf32-lo
    float* xsh = asl + 128 * XP2;         // [128][36] tf32-hi of x
    float* xsl = xsh + 128 * XP2;         // [128][36] tf32-lo
    float* wbh = xsl + 128 * XP2;         // [80][36]  weights hi ([c][k])
    float* wbl = wbh + 80 * XP2;          // [80][36]  weights lo
    float* str = wbl + 80 * XP2;          // [16][64]  tr_w transposed
    float* sinb = str + 16 * 64;          // [64]
    float* sdtb = sinb + 64;              // [16]
    float* scw = sdtb + 16;               // [32][4] conv_w chunk
    // epilogue overlays (main-loop arrays dead by then):
    float* sproj = ash;                   // [128][68]
    float* sdm = xsh;                     // [128][17]

    const int tid = threadIdx.x;
    const int base = blockIdx.x * 128;       // global row (b*T + t)
    const int t0 = base & (TT - 1);
    const int warp = tid >> 5, lane = tid & 31;
    const int wm = warp >> 1;                // 0..3: rows 32*wm
    const int wn = warp & 1;                 // 0..1: cols 40*wn
    const int g = lane >> 2, tg = lane & 3;

    // persistent small loads
    if (tid < 64) sinb[tid] = in_b[tid];
    else if (tid < 80) sdtb[tid - 64] = dt_b[tid - 64];
    for (int i = tid; i < 16 * 64; i += 256) {
        int n = i >> 4, r = i & 15;          // tr_w[n][r]
        str[r * 64 + n] = tr_w[i];
    }

    float4 acc[2][5];
#pragma unroll
    for (int i = 0; i < 2; i++)
#pragma unroll
        for (int j = 0; j < 5; j++) acc[i][j] = make_float4(0.f, 0.f, 0.f, 0.f);

    for (int k0 = 0; k0 < DD; k0 += 32) {
        // ---- load x chunk [131 rows][32 k], row-major (coalesced float4) ----
        for (int idx = tid; idx < NROW * 8; idx += 256) {
            int ri = idx >> 3, kq = idx & 7;
            int t = (ri < 128) ? (t0 + ri) : (t0 + ri - NROW);  // 128..130 -> t0-3..t0-1
            float4 v = make_float4(0.f, 0.f, 0.f, 0.f);
            if (t >= 0)
                v = *(const float4*)(x + (size_t)(base - t0 + t) * DD + k0 + 4 * kq);
            *(float4*)(xsf + ri * XP2 + 4 * kq) = v;
        }
        // ---- load weights [c][k] and split hi/lo ----
        for (int idx = tid; idx < 80 * 8; idx += 256) {
            int c = idx >> 3, kq = idx & 7;
            const float* src = (c < 64) ? (in_w + (size_t)c * DD)
                                        : (dt_w + (size_t)(c - 64) * DD);
            float4 v = *(const float4*)(src + k0 + 4 * kq);
            float vv[4] = {v.x, v.y, v.z, v.w};
#pragma unroll
            for (int q = 0; q < 4; q++) {
                uint32_t h = tf32_hi(vv[q]);
                wbh[c * XP2 + 4 * kq + q] = __uint_as_float(h);
                wbl[c * XP2 + 4 * kq + q] =
                    __uint_as_float(tf32_hi(vv[q] - __uint_as_float(h)));
            }
        }
        // ---- conv_w chunk ----
        if (tid < 128) scw[tid] = conv_w[(size_t)(k0 + (tid >> 2)) * KK + (tid & 3)];
        __syncthreads();

        // ---- build conv + split both operands ----
        for (int idx = tid; idx < 128 * 32; idx += 256) {
            int r = idx >> 5, kk = idx & 31;
            float xv = xsf[r * XP2 + kk];
            float c0 = scw[kk * 4 + 0], c1 = scw[kk * 4 + 1];
            float c2 = scw[kk * 4 + 2], c3 = scw[kk * 4 + 3];
            int rm1 = r - 1; if (rm1 < 0) rm1 += NROW;
            int rm2 = r - 2; if (rm2 < 0) rm2 += NROW;
            int rm3 = r - 3; if (rm3 < 0) rm3 += NROW;
            float v = fmaf(c3, xv, xv);
            v = fmaf(c2, xsf[rm1 * XP2 + kk], v);
            v = fmaf(c1, xsf[rm2 * XP2 + kk], v);
            v = fmaf(c0, xsf[rm3 * XP2 + kk], v);
            uint32_t ha = tf32_hi(v);
            ash[r * XP2 + kk] = __uint_as_float(ha);
            asl[r * XP2 + kk] = __uint_as_float(tf32_hi(v - __uint_as_float(ha)));
            uint32_t hx = tf32_hi(xv);
            xsh[r * XP2 + kk] = __uint_as_float(hx);
            xsl[r * XP2 + kk] = __uint_as_float(tf32_hi(xv - __uint_as_float(hx)));
        }
        __syncthreads();

        // ---- MMA: 4 k8 steps ----
#pragma unroll
        for (int ks = 0; ks < 4; ks++) {
            const int k8 = 8 * ks;
            // A fragments: conv operand (all warps)
            uint32_t cah[2][4], cal[2][4];
#pragma unroll
            for (int mf = 0; mf < 2; mf++) {
                int r0 = 32 * wm + 16 * mf + g;
                cah[mf][0] = __float_as_uint(ash[r0 * XP2 + k8 + tg]);
                cah[mf][1] = __float_as_uint(ash[(r0 + 8) * XP2 + k8 + tg]);
                cah[mf][2] = __float_as_uint(ash[r0 * XP2 + k8 + tg + 4]);
                cah[mf][3] = __float_as_uint(ash[(r0 + 8) * XP2 + k8 + tg + 4]);
                cal[mf][0] = __float_as_uint(asl[r0 * XP2 + k8 + tg]);
                cal[mf][1] = __float_as_uint(asl[(r0 + 8) * XP2 + k8 + tg]);
                cal[mf][2] = __float_as_uint(asl[r0 * XP2 + k8 + tg + 4]);
                cal[mf][3] = __float_as_uint(asl[(r0 + 8) * XP2 + k8 + tg + 4]);
            }
            // A fragments: x operand (dt cols; wn==1 warps only)
            uint32_t xah[2][4], xal[2][4];
            if (wn) {
#pragma unroll
                for (int mf = 0; mf < 2; mf++) {
                    int r0 = 32 * wm + 16 * mf + g;
                    xah[mf][0] = __float_as_uint(xsh[r0 * XP2 + k8 + tg]);
                    xah[mf][1] = __float_as_uint(xsh[(r0 + 8) * XP2 + k8 + tg]);
                    xah[mf][2] = __float_as_uint(xsh[r0 * XP2 + k8 + tg + 4]);
                    xah[mf][3] = __float_as_uint(xsh[(r0 + 8) * XP2 + k8 + tg + 4]);
                    xal[mf][0] = __float_as_uint(xsl[r0 * XP2 + k8 + tg]);
                    xal[mf][1] = __float_as_uint(xsl[(r0 + 8) * XP2 + k8 + tg]);
                    xal[mf][2] = __float_as_uint(xsl[r0 * XP2 + k8 + tg + 4]);
                    xal[mf][3] = __float_as_uint(xsl[(r0 + 8) * XP2 + k8 + tg + 4]);
                }
            }
            // B fragments
            uint32_t bh[5][2], bl[5][2];
#pragma unroll
            for (int nf = 0; nf < 5; nf++) {
                int c0 = 40 * wn + 8 * nf + g;
                bh[nf][0] = __float_as_uint(wbh[c0 * XP2 + k8 + tg]);
                bh[nf][1] = __float_as_uint(wbh[c0 * XP2 + k8 + tg + 4]);
                bl[nf][0] = __float_as_uint(wbl[c0 * XP2 + k8 + tg]);
                bl[nf][1] = __float_as_uint(wbl[c0 * XP2 + k8 + tg + 4]);
            }
            // MMAs
            if (wn == 0) {
#pragma unroll
                for (int mf = 0; mf < 2; mf++) {
                    MMA3(acc[mf][0], cah[mf], cal[mf], bh[0], bl[0]);
                    MMA3(acc[mf][1], cah[mf], cal[mf], bh[1], bl[1]);
                    MMA3(acc[mf][2], cah[mf], cal[mf], bh[2], bl[2]);
                    MMA3(acc[mf][3], cah[mf], cal[mf], bh[3], bl[3]);
                    MMA3(acc[mf][4], cah[mf], cal[mf], bh[4], bl[4]);
                }
            } else {
#pragma unroll
                for (int mf = 0; mf < 2; mf++) {
                    MMA3(acc[mf][0], cah[mf], cal[mf], bh[0], bl[0]);
                    MMA3(acc[mf][1], cah[mf], cal[mf], bh[1], bl[1]);
                    MMA3(acc[mf][2], cah[mf], cal[mf], bh[2], bl[2]);
                    MMA3(acc[mf][3], xah[mf], xal[mf], bh[3], bl[3]);
                    MMA3(acc[mf][4], xah[mf], xal[mf], bh[4], bl[4]);
                }
            }
        }
        __syncthreads();
    }

    // ---- epilogue: stage conv cols to sproj; tanh(dt_mid+dt_b) to sdm ----
#pragma unroll
    for (int mf = 0; mf < 2; mf++) {
        int r0 = 32 * wm + 16 * mf + g;
#pragma unroll
        for (int nf = 0; nf < 5; nf++) {
            if (wn == 1 && nf >= 3) continue;   // dt tiles handled below
            int c = 40 * wn + 8 * nf + 2 * tg;
            float4 v = acc[mf][nf];
            sproj[r0 * 68 + c] = v.x;
            sproj[r0 * 68 + c + 1] = v.y;
            sproj[(r0 + 8) * 68 + c] = v.z;
            sproj[(r0 + 8) * 68 + c + 1] = v.w;
        }
        if (wn == 1) {
#pragma unroll
            for (int nf = 3; nf < 5; nf++) {
                int c16 = 8 * (nf - 3) + 2 * tg;
                float4 v = acc[mf][nf];
                sdm[r0 * 17 + c16] = tanhf(v.x + sdtb[c16]);
                sdm[r0 * 17 + c16 + 1] = tanhf(v.y + sdtb[c16 + 1]);
                sdm[(r0 + 8) * 17 + c16] = tanhf(v.z + sdtb[c16]);
                sdm[(r0 + 8) * 17 + c16 + 1] = tanhf(v.w + sdtb[c16 + 1]);
            }
        }
    }
    __syncthreads();

    // ---- final: delta = sdm @ tr_w^T; write interleaved g_dp ----
    {
        int row = tid >> 1;
        int ch = (tid & 1) * 32;
        float dmv[16];
#pragma unroll
        for (int r = 0; r < 16; r++) dmv[r] = sdm[row * 17 + r];
        size_t grow = base + row;
#pragma unroll
        for (int j = 0; j < 32; j += 2) {
            int c = ch + j;
            float d0 = 0.f, d1 = 0.f;
#pragma unroll
            for (int r = 0; r < 16; r++) {
                d0 = fmaf(dmv[r], str[r * 64 + c], d0);
                d1 = fmaf(dmv[r], str[r * 64 + c + 1], d1);
            }
            float p0 = sproj[row * 68 + c] + sinb[c];
            float p1 = sproj[row * 68 + c + 1] + sinb[c + 1];
            *(float4*)((float*)(g_dp + grow * NN + c)) = make_float4(d0, p0, d1, p1);
        }
    }
}

// ---------------------------------------------------------------------------
// Stage 2: sequential scan, 256 chains, 24-cycle chain via MUFU.TANH.
// ---------------------------------------------------------------------------
__device__ __forceinline__ float fast_tanh(float v) {
    float r;
    asm("tanh.approx.f32 %0, %1;" : "=f"(r) : "f"(v));
    return r;
}

__global__ __launch_bounds__(32) void scan_kernel()
{
    const int chain = blockIdx.x * 32 + threadIdx.x;   // 8 blocks x 32 threads
    const int b = chain >> 6;
    const int n = chain & 63;
    const float2* pdp = g_dp + (size_t)b * TT * NN + n;
    float* ps = g_states + (size_t)b * TT * NN + n;

    float s = 0.f;

    float2 dpA[SG];   // .x = d/2, .y = p
#pragma unroll
    for (int i = 0; i < SG; i++) {
        float2 v = pdp[i * NN];
        dpA[i] = make_float2(0.5f * v.x, v.y);
    }

    for (int t0 = 0; t0 < TT; t0 += SG) {
        float2 dpB[SG];
        int tn = t0 + SG;
#pragma unroll
        for (int i = 0; i < SG; i++) dpB[i] = pdp[(tn + i) * NN];
#pragma unroll
        for (int i = 0; i < SG; i++) {
            float hd = dpA[i].x, p = dpA[i].y;
            float h = fmaf(s, 0.5f, hd);     // chain +4
            float th = fast_tanh(h);         // +16
            float hp = h + p;                // off-chain
            s = fmaf(h, th, hp);             // +4
            ps[(t0 + i) * NN] = s;
        }
#pragma unroll
        for (int i = 0; i < SG; i++) {
            dpA[i] = make_float2(0.5f * dpB[i].x, dpB[i].y);
        }
    }
}

// ---------------------------------------------------------------------------
// Stage 3: out = states @ out_w^T + out_b via split-tf32 mma.sync.
// Block 128(M) x 64(N), 8 warps, warp tile 32x32 (2 m16 x 4 n8), K=64.
// ---------------------------------------------------------------------------
#define S3PAD 68

__global__ __launch_bounds__(256) void stage3_kernel(
    const float* __restrict__ out_w,
    const float* __restrict__ out_b,
    float* __restrict__ out)
{
    extern __shared__ float smem3[];
    float* sA = smem3;                 // [128][S3PAD]
    float* sB = smem3 + 128 * S3PAD;   // [64][S3PAD]

    const int tid = threadIdx.x;
    const int rbase = blockIdx.y * 128;
    const int cbase = blockIdx.x * 64;
    const int warp = tid >> 5;
    const int lane = tid & 31;
    const int wm = warp >> 1;
    const int wn = warp & 1;
    const int g = lane >> 2;
    const int tg = lane & 3;

    for (int idx = tid; idx < 128 * 16; idx += 256) {
        int r = idx >> 4, q = idx & 15;
        float4 v = *(const float4*)(g_states + (size_t)(rbase + r) * NN + 4 * q);
        *(float4*)(sA + r * S3PAD + 4 * q) = v;
    }
    for (int idx = tid; idx < 64 * 16; idx += 256) {
        int c = idx >> 4, q = idx & 15;
        float4 v = *(const float4*)(out_w + (size_t)(cbase + c) * NN + 4 * q);
        *(float4*)(sB + c * S3PAD + 4 * q) = v;
    }
    __syncthreads();

    float4 acc[2][4];
#pragma unroll
    for (int i = 0; i < 2; i++)
#pragma unroll
        for (int j = 0; j < 4; j++) acc[i][j] = make_float4(0.f, 0.f, 0.f, 0.f);

#pragma unroll
    for (int k0 = 0; k0 < 64; k0 += 8) {
        uint32_t ahi[2][4], alo[2][4];
#pragma unroll
        for (int mf = 0; mf < 2; mf++) {
            int r0 = wm * 32 + mf * 16 + g;
            float av[4];
            av[0] = sA[r0 * S3PAD + k0 + tg];
            av[1] = sA[(r0 + 8) * S3PAD + k0 + tg];
            av[2] = sA[r0 * S3PAD + k0 + tg + 4];
            av[3] = sA[(r0 + 8) * S3PAD + k0 + tg + 4];
#pragma unroll
            for (int q = 0; q < 4; q++) {
                uint32_t h = tf32_hi(av[q]);
                ahi[mf][q] = h;
                alo[mf][q] = tf32_hi(av[q] - __uint_as_float(h));
            }
        }
        uint32_t bhi[4][2], blo[4][2];
#pragma unroll
        for (int nf = 0; nf < 4; nf++) {
            int c0 = wn * 32 + nf * 8 + g;
            float bv[2];
            bv[0] = sB[c0 * S3PAD + k0 + tg];
            bv[1] = sB[c0 * S3PAD + k0 + tg + 4];
#pragma unroll
            for (int q = 0; q < 2; q++) {
                uint32_t h = tf32_hi(bv[q]);
                bhi[nf][q] = h;
                blo[nf][q] = tf32_hi(bv[q] - __uint_as_float(h));
            }
        }
#pragma unroll
        for (int mf = 0; mf < 2; mf++) {
#pragma unroll
            for (int nf = 0; nf < 4; nf++) {
                MMA3(acc[mf][nf], ahi[mf], alo[mf], bhi[nf], blo[nf]);
            }
        }
    }

#pragma unroll
    for (int nf = 0; nf < 4; nf++) {
        int c = cbase + wn * 32 + nf * 8 + 2 * tg;
        float b0 = out_b[c], b1 = out_b[c + 1];
#pragma unroll
        for (int mf = 0; mf < 2; mf++) {
            int r0 = rbase + wm * 32 + mf * 16 + g;
            float4 v = acc[mf][nf];
            *(float2*)(out + (size_t)r0 * DD + c) = make_float2(v.x + b0, v.y + b1);
            *(float2*)(out + (size_t)(r0 + 8) * DD + c) = make_float2(v.z + b0, v.w + b1);
        }
    }
}

// ---------------------------------------------------------------------------
extern "C" void kernel_launch(void* const* d_in, const int* in_sizes, int n_in,
                              void* d_out, int out_size)
{
    const float* x      = (const float*)d_in[0];
    const float* conv_w = (const float*)d_in[1];
    const float* in_w   = (const float*)d_in[2];
    const float* in_b   = (const float*)d_in[3];
    const float* dt_w   = (const float*)d_in[4];
    const float* dt_b   = (const float*)d_in[5];
    const float* tr_w   = (const float*)d_in[6];
    const float* out_w  = (const float*)d_in[7];
    const float* out_b  = (const float*)d_in[8];
    float* out = (float*)d_out;

    const int s1_smem = (NROW * XP2 + 4 * 128 * XP2 + 2 * 80 * XP2 +
                         16 * 64 + 64 + 16 + 128) * sizeof(float);   // 120560 B
    cudaFuncSetAttribute(stage1_kernel,
                         cudaFuncAttributeMaxDynamicSharedMemorySize, s1_smem);
    const int s3_smem = (128 + 64) * S3PAD * sizeof(float);  // 52224 B
    cudaFuncSetAttribute(stage3_kernel,
                         cudaFuncAttributeMaxDynamicSharedMemorySize, s3_smem);

    stage1_kernel<<<128, 256, s1_smem>>>(x, conv_w, in_w, in_b, dt_w, dt_b, tr_w);
    scan_kernel<<<8, 32>>>();
    stage3_kernel<<<dim3(16, 128), 256, s3_smem>>>(out_w, out_b, out);
}

// round 10
// speedup vs baseline: 1.0264x; 1.0264x over previous
#include <cuda_runtime.h>
#include <cstddef>
#include <cstdint>

#define BB 4
#define TT 4096
#define DD 1024
#define NN 64
#define RR 16
#define KK 4
#define BT (BB * TT)
#define SG 32    // scan prefetch group size

// Scratch (device globals — no allocation allowed)
__device__ float2 g_dp[BT * NN + SG * NN];    // interleaved {delta, proj}; padded tail
__device__ float g_states[BT * NN];
__device__ float g_wh[80 * DD];               // pre-split weights hi, [c][k]
__device__ float g_wl[80 * DD];               // pre-split weights lo

// ---------------------------------------------------------------------------
// tf32 helpers (fragment layout verified in rounds 8/9)
// ---------------------------------------------------------------------------
__device__ __forceinline__ uint32_t tf32_hi(float x) {
    uint32_t r;
    asm("cvt.rna.tf32.f32 %0, %1;" : "=r"(r) : "f"(x));
    return r;
}
__device__ __forceinline__ void mma_tf32(float4& d,
                                         uint32_t a0, uint32_t a1, uint32_t a2, uint32_t a3,
                                         uint32_t b0, uint32_t b1) {
    asm("mma.sync.aligned.m16n8k8.row.col.f32.tf32.tf32.f32 "
        "{%0,%1,%2,%3}, {%4,%5,%6,%7}, {%8,%9}, {%0,%1,%2,%3};"
        : "+f"(d.x), "+f"(d.y), "+f"(d.z), "+f"(d.w)
        : "r"(a0), "r"(a1), "r"(a2), "r"(a3), "r"(b0), "r"(b1));
}
// 3-pass split-tf32: D += alo*bhi + ahi*blo + ahi*bhi
#define MMA3(ACC, AH, AL, BH, BL)                                          \
    do {                                                                   \
        mma_tf32(ACC, AL[0], AL[1], AL[2], AL[3], BH[0], BH[1]);           \
        mma_tf32(ACC, AH[0], AH[1], AH[2], AH[3], BL[0], BL[1]);           \
        mma_tf32(ACC, AH[0], AH[1], AH[2], AH[3], BH[0], BH[1]);           \
    } while (0)

// ---------------------------------------------------------------------------
// Prep: split in_w/dt_w into tf32 hi/lo once. [c][k], c<64 -> in_w else dt_w.
// ---------------------------------------------------------------------------
__global__ void prep_w_kernel(const float* __restrict__ in_w,
                              const float* __restrict__ dt_w)
{
    int idx = blockIdx.x * 256 + threadIdx.x;
    if (idx >= 80 * DD) return;
    int c = idx >> 10, k = idx & (DD - 1);
    float v = (c < 64) ? in_w[(size_t)c * DD + k] : dt_w[(size_t)(c - 64) * DD + k];
    uint32_t h = tf32_hi(v);
    g_wh[idx] = __uint_as_float(h);
    g_wl[idx] = __uint_as_float(tf32_hi(v - __uint_as_float(h)));
}

// ---------------------------------------------------------------------------
// Stage 1 (fused): 64-row tiles, full K=1024, split-tf32 MMA.
//   proj  = (x + causal_conv(x)) @ in_w^T + in_b      (cols 0..63)
//   delta = tanh(x @ dt_w^T + dt_b) @ tr_w^T          (via dt cols 64..79)
// grid 256, block 128 (4 warps). Warp tile 32 rows x 40 cols. dt cols use A=x.
// ---------------------------------------------------------------------------
#define XP2 36    // [row][k] smem pitch
#define NROW 67   // 64 rows + 3 halo (idx 64..66 = t0-3..t0-1)

__global__ __launch_bounds__(128) void stage1_kernel(
    const float* __restrict__ x,
    const float* __restrict__ conv_w,
    const float* __restrict__ in_b,
    const float* __restrict__ dt_b,
    const float* __restrict__ tr_w)
{
    extern __shared__ float s1[];
    float* xsf = s1;                      // [67][36] fp32 x chunk
    float* ash = xsf + NROW * XP2;        // [64][36] tf32-hi of (x+conv)
    float* asl = ash + 64 * XP2;          // [64][36] tf32-lo
    float* xsh = asl + 64 * XP2;          // [64][36] tf32-hi of x
    float* xsl = xsh + 64 * XP2;          // [64][36] tf32-lo
    float* wbh = xsl + 64 * XP2;          // [80][36]  weights hi ([c][k])
    float* wbl = wbh + 80 * XP2;          // [80][36]  weights lo
    float* str = wbl + 80 * XP2;          // [16][64]  tr_w transposed
    float* sinb = str + 16 * 64;          // [64]
    float* sdtb = sinb + 64;              // [16]
    float* scw = sdtb + 16;               // [32][4] conv_w chunk
    // epilogue overlays (main-loop arrays dead by then):
    float* sproj = ash;                   // [64][68] (spans ash+asl)
    float* sdm = xsh;                     // [64][17]

    const int tid = threadIdx.x;
    const int base = blockIdx.x * 64;        // global row (b*T + t)
    const int t0 = base & (TT - 1);
    const int warp = tid >> 5, lane = tid & 31;
    const int wm = warp >> 1;                // 0..1: rows 32*wm
    const int wn = warp & 1;                 // 0..1: cols 40*wn
    const int g = lane >> 2, tg = lane & 3;

    // persistent small loads
    if (tid < 64) sinb[tid] = in_b[tid];
    else if (tid < 80) sdtb[tid - 64] = dt_b[tid - 64];
    for (int i = tid; i < 16 * 64; i += 128) {
        int n = i >> 4, r = i & 15;          // tr_w[n][r]
        str[r * 64 + n] = tr_w[i];
    }

    float4 acc[2][5];
#pragma unroll
    for (int i = 0; i < 2; i++)
#pragma unroll
        for (int j = 0; j < 5; j++) acc[i][j] = make_float4(0.f, 0.f, 0.f, 0.f);

    for (int k0 = 0; k0 < DD; k0 += 32) {
        // ---- load x chunk [67 rows][32 k], row-major (coalesced float4) ----
        for (int idx = tid; idx < NROW * 8; idx += 128) {
            int ri = idx >> 3, kq = idx & 7;
            int t = (ri < 64) ? (t0 + ri) : (t0 + ri - NROW);  // 64..66 -> t0-3..t0-1
            float4 v = make_float4(0.f, 0.f, 0.f, 0.f);
            if (t >= 0)
                v = *(const float4*)(x + (size_t)(base - t0 + t) * DD + k0 + 4 * kq);
            *(float4*)(xsf + ri * XP2 + 4 * kq) = v;
        }
        // ---- copy pre-split weights [c][k0..k0+32] (coalesced float4) ----
        for (int idx = tid; idx < 80 * 8; idx += 128) {
            int c = idx >> 3, kq = idx & 7;
            *(float4*)(wbh + c * XP2 + 4 * kq) =
                *(const float4*)(g_wh + (size_t)c * DD + k0 + 4 * kq);
            *(float4*)(wbl + c * XP2 + 4 * kq) =
                *(const float4*)(g_wl + (size_t)c * DD + k0 + 4 * kq);
        }
        // ---- conv_w chunk ----
        if (tid < 128) scw[tid] = conv_w[(size_t)(k0 + (tid >> 2)) * KK + (tid & 3)];
        __syncthreads();

        // ---- build conv + split both A operands ----
        for (int idx = tid; idx < 64 * 32; idx += 128) {
            int r = idx >> 5, kk = idx & 31;
            float xv = xsf[r * XP2 + kk];
            float c0 = scw[kk * 4 + 0], c1 = scw[kk * 4 + 1];
            float c2 = scw[kk * 4 + 2], c3 = scw[kk * 4 + 3];
            int rm1 = r - 1; if (rm1 < 0) rm1 += NROW;
            int rm2 = r - 2; if (rm2 < 0) rm2 += NROW;
            int rm3 = r - 3; if (rm3 < 0) rm3 += NROW;
            float v = fmaf(c3, xv, xv);
            v = fmaf(c2, xsf[rm1 * XP2 + kk], v);
            v = fmaf(c1, xsf[rm2 * XP2 + kk], v);
            v = fmaf(c0, xsf[rm3 * XP2 + kk], v);
            uint32_t ha = tf32_hi(v);
            ash[r * XP2 + kk] = __uint_as_float(ha);
            asl[r * XP2 + kk] = __uint_as_float(tf32_hi(v - __uint_as_float(ha)));
            uint32_t hx = tf32_hi(xv);
            xsh[r * XP2 + kk] = __uint_as_float(hx);
            xsl[r * XP2 + kk] = __uint_as_float(tf32_hi(xv - __uint_as_float(hx)));
        }
        __syncthreads();

        // ---- MMA: 4 k8 steps ----
#pragma unroll
        for (int ks = 0; ks < 4; ks++) {
            const int k8 = 8 * ks;
            // A fragments: conv operand (all warps)
            uint32_t cah[2][4], cal[2][4];
#pragma unroll
            for (int mf = 0; mf < 2; mf++) {
                int r0 = 32 * wm + 16 * mf + g;
                cah[mf][0] = __float_as_uint(ash[r0 * XP2 + k8 + tg]);
                cah[mf][1] = __float_as_uint(ash[(r0 + 8) * XP2 + k8 + tg]);
                cah[mf][2] = __float_as_uint(ash[r0 * XP2 + k8 + tg + 4]);
                cah[mf][3] = __float_as_uint(ash[(r0 + 8) * XP2 + k8 + tg + 4]);
                cal[mf][0] = __float_as_uint(asl[r0 * XP2 + k8 + tg]);
                cal[mf][1] = __float_as_uint(asl[(r0 + 8) * XP2 + k8 + tg]);
                cal[mf][2] = __float_as_uint(asl[r0 * XP2 + k8 + tg + 4]);
                cal[mf][3] = __float_as_uint(asl[(r0 + 8) * XP2 + k8 + tg + 4]);
            }
            // A fragments: x operand (dt cols; wn==1 warps only)
            uint32_t xah[2][4], xal[2][4];
            if (wn) {
#pragma unroll
                for (int mf = 0; mf < 2; mf++) {
                    int r0 = 32 * wm + 16 * mf + g;
                    xah[mf][0] = __float_as_uint(xsh[r0 * XP2 + k8 + tg]);
                    xah[mf][1] = __float_as_uint(xsh[(r0 + 8) * XP2 + k8 + tg]);
                    xah[mf][2] = __float_as_uint(xsh[r0 * XP2 + k8 + tg + 4]);
                    xah[mf][3] = __float_as_uint(xsh[(r0 + 8) * XP2 + k8 + tg + 4]);
                    xal[mf][0] = __float_as_uint(xsl[r0 * XP2 + k8 + tg]);
                    xal[mf][1] = __float_as_uint(xsl[(r0 + 8) * XP2 + k8 + tg]);
                    xal[mf][2] = __float_as_uint(xsl[r0 * XP2 + k8 + tg + 4]);
                    xal[mf][3] = __float_as_uint(xsl[(r0 + 8) * XP2 + k8 + tg + 4]);
                }
            }
            // B fragments
            uint32_t bh[5][2], bl[5][2];
#pragma unroll
            for (int nf = 0; nf < 5; nf++) {
                int c0 = 40 * wn + 8 * nf + g;
                bh[nf][0] = __float_as_uint(wbh[c0 * XP2 + k8 + tg]);
                bh[nf][1] = __float_as_uint(wbh[c0 * XP2 + k8 + tg + 4]);
                bl[nf][0] = __float_as_uint(wbl[c0 * XP2 + k8 + tg]);
                bl[nf][1] = __float_as_uint(wbl[c0 * XP2 + k8 + tg + 4]);
            }
            // MMAs
            if (wn == 0) {
#pragma unroll
                for (int mf = 0; mf < 2; mf++) {
                    MMA3(acc[mf][0], cah[mf], cal[mf], bh[0], bl[0]);
                    MMA3(acc[mf][1], cah[mf], cal[mf], bh[1], bl[1]);
                    MMA3(acc[mf][2], cah[mf], cal[mf], bh[2], bl[2]);
                    MMA3(acc[mf][3], cah[mf], cal[mf], bh[3], bl[3]);
                    MMA3(acc[mf][4], cah[mf], cal[mf], bh[4], bl[4]);
                }
            } else {
#pragma unroll
                for (int mf = 0; mf < 2; mf++) {
                    MMA3(acc[mf][0], cah[mf], cal[mf], bh[0], bl[0]);
                    MMA3(acc[mf][1], cah[mf], cal[mf], bh[1], bl[1]);
                    MMA3(acc[mf][2], cah[mf], cal[mf], bh[2], bl[2]);
                    MMA3(acc[mf][3], xah[mf], xal[mf], bh[3], bl[3]);
                    MMA3(acc[mf][4], xah[mf], xal[mf], bh[4], bl[4]);
                }
            }
        }
        __syncthreads();
    }

    // ---- epilogue: stage conv cols to sproj; tanh(dt_mid+dt_b) to sdm ----
#pragma unroll
    for (int mf = 0; mf < 2; mf++) {
        int r0 = 32 * wm + 16 * mf + g;
#pragma unroll
        for (int nf = 0; nf < 5; nf++) {
            if (wn == 1 && nf >= 3) continue;   // dt tiles handled below
            int c = 40 * wn + 8 * nf + 2 * tg;
            float4 v = acc[mf][nf];
            sproj[r0 * 68 + c] = v.x;
            sproj[r0 * 68 + c + 1] = v.y;
            sproj[(r0 + 8) * 68 + c] = v.z;
            sproj[(r0 + 8) * 68 + c + 1] = v.w;
        }
        if (wn == 1) {
#pragma unroll
            for (int nf = 3; nf < 5; nf++) {
                int c16 = 8 * (nf - 3) + 2 * tg;
                float4 v = acc[mf][nf];
                sdm[r0 * 17 + c16] = tanhf(v.x + sdtb[c16]);
                sdm[r0 * 17 + c16 + 1] = tanhf(v.y + sdtb[c16 + 1]);
                sdm[(r0 + 8) * 17 + c16] = tanhf(v.z + sdtb[c16]);
                sdm[(r0 + 8) * 17 + c16 + 1] = tanhf(v.w + sdtb[c16 + 1]);
            }
        }
    }
    __syncthreads();

    // ---- final: delta = sdm @ tr_w^T; write interleaved g_dp ----
    {
        int row = tid >> 1;                 // 0..63
        int ch = (tid & 1) * 32;
        float dmv[16];
#pragma unroll
        for (int r = 0; r < 16; r++) dmv[r] = sdm[row * 17 + r];
        size_t grow = base + row;
#pragma unroll
        for (int j = 0; j < 32; j += 2) {
            int c = ch + j;
            float d0 = 0.f, d1 = 0.f;
#pragma unroll
            for (int r = 0; r < 16; r++) {
                d0 = fmaf(dmv[r], str[r * 64 + c], d0);
                d1 = fmaf(dmv[r], str[r * 64 + c + 1], d1);
            }
            float p0 = sproj[row * 68 + c] + sinb[c];
            float p1 = sproj[row * 68 + c + 1] + sinb[c + 1];
            *(float4*)((float*)(g_dp + grow * NN + c)) = make_float4(d0, p0, d1, p1);
        }
    }
}

// ---------------------------------------------------------------------------
// Stage 2: sequential scan, 256 chains, 24-cycle chain via MUFU.TANH.
// ---------------------------------------------------------------------------
__device__ __forceinline__ float fast_tanh(float v) {
    float r;
    asm("tanh.approx.f32 %0, %1;" : "=f"(r) : "f"(v));
    return r;
}

__global__ __launch_bounds__(32) void scan_kernel()
{
    const int chain = blockIdx.x * 32 + threadIdx.x;   // 8 blocks x 32 threads
    const int b = chain >> 6;
    const int n = chain & 63;
    const float2* pdp = g_dp + (size_t)b * TT * NN + n;
    float* ps = g_states + (size_t)b * TT * NN + n;

    float s = 0.f;

    float2 dpA[SG];   // .x = d/2, .y = p
#pragma unroll
    for (int i = 0; i < SG; i++) {
        float2 v = pdp[i * NN];
        dpA[i] = make_float2(0.5f * v.x, v.y);
    }

    for (int t0 = 0; t0 < TT; t0 += SG) {
        float2 dpB[SG];
        int tn = t0 + SG;
#pragma unroll
        for (int i = 0; i < SG; i++) dpB[i] = pdp[(tn + i) * NN];
#pragma unroll
        for (int i = 0; i < SG; i++) {
            float hd = dpA[i].x, p = dpA[i].y;
            float h = fmaf(s, 0.5f, hd);     // chain +4
            float th = fast_tanh(h);         // +16
            float hp = h + p;                // off-chain
            s = fmaf(h, th, hp);             // +4
            ps[(t0 + i) * NN] = s;
        }
#pragma unroll
        for (int i = 0; i < SG; i++) {
            dpA[i] = make_float2(0.5f * dpB[i].x, dpB[i].y);
        }
    }
}

// ---------------------------------------------------------------------------
// Stage 3: out = states @ out_w^T + out_b via split-tf32 mma.sync.
// Block 128(M) x 64(N), 8 warps, warp tile 32x32 (2 m16 x 4 n8), K=64.
// ---------------------------------------------------------------------------
#define S3PAD 68

__global__ __launch_bounds__(256) void stage3_kernel(
    const float* __restrict__ out_w,
    const float* __restrict__ out_b,
    float* __restrict__ out)
{
    extern __shared__ float smem3[];
    float* sA = smem3;                 // [128][S3PAD]
    float* sB = smem3 + 128 * S3PAD;   // [64][S3PAD]

    const int tid = threadIdx.x;
    const int rbase = blockIdx.y * 128;
    const int cbase = blockIdx.x * 64;
    const int warp = tid >> 5;
    const int lane = tid & 31;
    const int wm = warp >> 1;
    const int wn = warp & 1;
    const int g = lane >> 2;
    const int tg = lane & 3;

    for (int idx = tid; idx < 128 * 16; idx += 256) {
        int r = idx >> 4, q = idx & 15;
        float4 v = *(const float4*)(g_states + (size_t)(rbase + r) * NN + 4 * q);
        *(float4*)(sA + r * S3PAD + 4 * q) = v;
    }
    for (int idx = tid; idx < 64 * 16; idx += 256) {
        int c = idx >> 4, q = idx & 15;
        float4 v = *(const float4*)(out_w + (size_t)(cbase + c) * NN + 4 * q);
        *(float4*)(sB + c * S3PAD + 4 * q) = v;
    }
    __syncthreads();

    float4 acc[2][4];
#pragma unroll
    for (int i = 0; i < 2; i++)
#pragma unroll
        for (int j = 0; j < 4; j++) acc[i][j] = make_float4(0.f, 0.f, 0.f, 0.f);

#pragma unroll
    for (int k0 = 0; k0 < 64; k0 += 8) {
        uint32_t ahi[2][4], alo[2][4];
#pragma unroll
        for (int mf = 0; mf < 2; mf++) {
            int r0 = wm * 32 + mf * 16 + g;
            float av[4];
            av[0] = sA[r0 * S3PAD + k0 + tg];
            av[1] = sA[(r0 + 8) * S3PAD + k0 + tg];
            av[2] = sA[r0 * S3PAD + k0 + tg + 4];
            av[3] = sA[(r0 + 8) * S3PAD + k0 + tg + 4];
#pragma unroll
            for (int q = 0; q < 4; q++) {
                uint32_t h = tf32_hi(av[q]);
                ahi[mf][q] = h;
                alo[mf][q] = tf32_hi(av[q] - __uint_as_float(h));
            }
        }
        uint32_t bhi[4][2], blo[4][2];
#pragma unroll
        for (int nf = 0; nf < 4; nf++) {
            int c0 = wn * 32 + nf * 8 + g;
            float bv[2];
            bv[0] = sB[c0 * S3PAD + k0 + tg];
            bv[1] = sB[c0 * S3PAD + k0 + tg + 4];
#pragma unroll
            for (int q = 0; q < 2; q++) {
                uint32_t h = tf32_hi(bv[q]);
                bhi[nf][q] = h;
                blo[nf][q] = tf32_hi(bv[q] - __uint_as_float(h));
            }
        }
#pragma unroll
        for (int mf = 0; mf < 2; mf++) {
#pragma unroll
            for (int nf = 0; nf < 4; nf++) {
                MMA3(acc[mf][nf], ahi[mf], alo[mf], bhi[nf], blo[nf]);
            }
        }
    }

#pragma unroll
    for (int nf = 0; nf < 4; nf++) {
        int c = cbase + wn * 32 + nf * 8 + 2 * tg;
        float b0 = out_b[c], b1 = out_b[c + 1];
#pragma unroll
        for (int mf = 0; mf < 2; mf++) {
            int r0 = rbase + wm * 32 + mf * 16 + g;
            float4 v = acc[mf][nf];
            *(float2*)(out + (size_t)r0 * DD + c) = make_float2(v.x + b0, v.y + b1);
            *(float2*)(out + (size_t)(r0 + 8) * DD + c) = make_float2(v.z + b0, v.w + b1);
        }
    }
}

// ---------------------------------------------------------------------------
extern "C" void kernel_launch(void* const* d_in, const int* in_sizes, int n_in,
                              void* d_out, int out_size)
{
    const float* x      = (const float*)d_in[0];
    const float* conv_w = (const float*)d_in[1];
    const float* in_w   = (const float*)d_in[2];
    const float* in_b   = (const float*)d_in[3];
    const float* dt_w   = (const float*)d_in[4];
    const float* dt_b   = (const float*)d_in[5];
    const float* tr_w   = (const float*)d_in[6];
    const float* out_w  = (const float*)d_in[7];
    const float* out_b  = (const float*)d_in[8];
    float* out = (float*)d_out;

    const int s1_smem = (NROW * XP2 + 4 * 64 * XP2 + 2 * 80 * XP2 +
                         16 * 64 + 64 + 16 + 128) * sizeof(float);   // 74480 B
    cudaFuncSetAttribute(stage1_kernel,
                         cudaFuncAttributeMaxDynamicSharedMemorySize, s1_smem);
    const int s3_smem = (128 + 64) * S3PAD * sizeof(float);  // 52224 B
    cudaFuncSetAttribute(stage3_kernel,
                         cudaFuncAttributeMaxDynamicSharedMemorySize, s3_smem);

    prep_w_kernel<<<320, 256>>>(in_w, dt_w);
    stage1_kernel<<<256, 128, s1_smem>>>(x, conv_w, in_b, dt_b, tr_w);
    scan_kernel<<<8, 32>>>();
    stage3_kernel<<<dim3(16, 128), 256, s3_smem>>>(out_w, out_b, out);
}

// round 11
// speedup vs baseline: 1.2920x; 1.2588x over previous
#include <cuda_runtime.h>
#include <cstddef>
#include <cstdint>

#define BB 4
#define TT 4096
#define DD 1024
#define NN 64
#define RR 16
#define KK 4
#define BT (BB * TT)
#define SG 32    // scan prefetch group size

// Scratch (device globals — no allocation allowed)
__device__ float g_mid[4 * 80 * BT];          // split-K partials, [kc][col][row]
__device__ float2 g_dp[BT * NN + SG * NN];    // interleaved {delta, proj}; padded tail
__device__ float g_states[BT * NN];
__device__ float g_wh[80 * DD];               // pre-split weights hi, [c][k]
__device__ float g_wl[80 * DD];               // pre-split weights lo

// ---------------------------------------------------------------------------
// tf32 helpers (fragment layout verified in rounds 8-10)
// ---------------------------------------------------------------------------
__device__ __forceinline__ uint32_t tf32_hi(float x) {
    uint32_t r;
    asm("cvt.rna.tf32.f32 %0, %1;" : "=r"(r) : "f"(x));
    return r;
}
__device__ __forceinline__ void mma_tf32(float4& d,
                                         uint32_t a0, uint32_t a1, uint32_t a2, uint32_t a3,
                                         uint32_t b0, uint32_t b1) {
    asm("mma.sync.aligned.m16n8k8.row.col.f32.tf32.tf32.f32 "
        "{%0,%1,%2,%3}, {%4,%5,%6,%7}, {%8,%9}, {%0,%1,%2,%3};"
        : "+f"(d.x), "+f"(d.y), "+f"(d.z), "+f"(d.w)
        : "r"(a0), "r"(a1), "r"(a2), "r"(a3), "r"(b0), "r"(b1));
}
// 3-pass split-tf32: D += alo*bhi + ahi*blo + ahi*bhi
#define MMA3(ACC, AH, AL, BH, BL)                                          \
    do {                                                                   \
        mma_tf32(ACC, AL[0], AL[1], AL[2], AL[3], BH[0], BH[1]);           \
        mma_tf32(ACC, AH[0], AH[1], AH[2], AH[3], BL[0], BL[1]);           \
        mma_tf32(ACC, AH[0], AH[1], AH[2], AH[3], BH[0], BH[1]);           \
    } while (0)

// ---------------------------------------------------------------------------
// Prep: split in_w/dt_w into tf32 hi/lo once. [c][k], c<64 -> in_w else dt_w.
// ---------------------------------------------------------------------------
__global__ void prep_w_kernel(const float* __restrict__ in_w,
                              const float* __restrict__ dt_w)
{
    int idx = blockIdx.x * 256 + threadIdx.x;
    if (idx >= 80 * DD) return;
    int c = idx >> 10, k = idx & (DD - 1);
    float v = (c < 64) ? in_w[(size_t)c * DD + k] : dt_w[(size_t)(c - 64) * DD + k];
    uint32_t h = tf32_hi(v);
    g_wh[idx] = __uint_as_float(h);
    g_wl[idx] = __uint_as_float(tf32_hi(v - __uint_as_float(h)));
}

// ---------------------------------------------------------------------------
// Stage 1a: split-K MMA partials. grid (4, 256): kc = K-chunk (256 wide),
// 64-row tile. Block 256 (8 warps). Warp tile 16 rows x 40 cols:
// wm = warp&3 (rows 16*wm), wn = warp>>2 (cols 40*wn). dt cols (64..79,
// i.e. wn==1 nf>=3) use A = x instead of x+conv.
// ---------------------------------------------------------------------------
#define XP2 36    // [row][k] smem pitch
#define NROW 67   // 64 rows + 3 halo (idx 64..66 = t0-3..t0-1)

__global__ __launch_bounds__(256) void stage1a_kernel(
    const float* __restrict__ x,
    const float* __restrict__ conv_w)
{
    extern __shared__ float s1[];
    float* xsf = s1;                      // [67][36] fp32 x chunk
    float* ash = xsf + NROW * XP2;        // [64][36] tf32-hi of (x+conv)
    float* asl = ash + 64 * XP2;          // [64][36] tf32-lo
    float* xsh = asl + 64 * XP2;          // [64][36] tf32-hi of x
    float* xsl = xsh + 64 * XP2;          // [64][36] tf32-lo
    float* wbh = xsl + 64 * XP2;          // [80][36]  weights hi ([c][k])
    float* wbl = wbh + 80 * XP2;          // [80][36]  weights lo
    float* scw = wbl + 80 * XP2;          // [32][4] conv_w chunk

    const int tid = threadIdx.x;
    const int koff = blockIdx.x * 256;
    const int base = blockIdx.y * 64;        // global row (b*T + t)
    const int t0 = base & (TT - 1);
    const int warp = tid >> 5, lane = tid & 31;
    const int wm = warp & 3;                 // rows 16*wm
    const int wn = warp >> 2;                // cols 40*wn
    const int g = lane >> 2, tg = lane & 3;

    float4 acc[5];
#pragma unroll
    for (int j = 0; j < 5; j++) acc[j] = make_float4(0.f, 0.f, 0.f, 0.f);

    for (int k0 = koff; k0 < koff + 256; k0 += 32) {
        // ---- load x chunk [67 rows][32 k], row-major (coalesced float4) ----
        for (int idx = tid; idx < NROW * 8; idx += 256) {
            int ri = idx >> 3, kq = idx & 7;
            int t = (ri < 64) ? (t0 + ri) : (t0 + ri - NROW);  // 64..66 -> t0-3..t0-1
            float4 v = make_float4(0.f, 0.f, 0.f, 0.f);
            if (t >= 0)
                v = *(const float4*)(x + (size_t)(base - t0 + t) * DD + k0 + 4 * kq);
            *(float4*)(xsf + ri * XP2 + 4 * kq) = v;
        }
        // ---- copy pre-split weights (coalesced float4) ----
        for (int idx = tid; idx < 80 * 8; idx += 256) {
            int c = idx >> 3, kq = idx & 7;
            *(float4*)(wbh + c * XP2 + 4 * kq) =
                *(const float4*)(g_wh + (size_t)c * DD + k0 + 4 * kq);
            *(float4*)(wbl + c * XP2 + 4 * kq) =
                *(const float4*)(g_wl + (size_t)c * DD + k0 + 4 * kq);
        }
        // ---- conv_w chunk ----
        if (tid < 128) scw[tid] = conv_w[(size_t)(k0 + (tid >> 2)) * KK + (tid & 3)];
        __syncthreads();

        // ---- build conv + split both A operands ----
        for (int idx = tid; idx < 64 * 32; idx += 256) {
            int r = idx >> 5, kk = idx & 31;
            float xv = xsf[r * XP2 + kk];
            float c0 = scw[kk * 4 + 0], c1 = scw[kk * 4 + 1];
            float c2 = scw[kk * 4 + 2], c3 = scw[kk * 4 + 3];
            int rm1 = r - 1; if (rm1 < 0) rm1 += NROW;
            int rm2 = r - 2; if (rm2 < 0) rm2 += NROW;
            int rm3 = r - 3; if (rm3 < 0) rm3 += NROW;
            float v = fmaf(c3, xv, xv);
            v = fmaf(c2, xsf[rm1 * XP2 + kk], v);
            v = fmaf(c1, xsf[rm2 * XP2 + kk], v);
            v = fmaf(c0, xsf[rm3 * XP2 + kk], v);
            uint32_t ha = tf32_hi(v);
            ash[r * XP2 + kk] = __uint_as_float(ha);
            asl[r * XP2 + kk] = __uint_as_float(tf32_hi(v - __uint_as_float(ha)));
            uint32_t hx = tf32_hi(xv);
            xsh[r * XP2 + kk] = __uint_as_float(hx);
            xsl[r * XP2 + kk] = __uint_as_float(tf32_hi(xv - __uint_as_float(hx)));
        }
        __syncthreads();

        // ---- MMA: 4 k8 steps, warp tile 16x40 ----
#pragma unroll
        for (int ks = 0; ks < 4; ks++) {
            const int k8 = 8 * ks;
            const int r0 = 16 * wm + g;
            // A fragments: conv operand
            uint32_t cah[4], cal[4];
            cah[0] = __float_as_uint(ash[r0 * XP2 + k8 + tg]);
            cah[1] = __float_as_uint(ash[(r0 + 8) * XP2 + k8 + tg]);
            cah[2] = __float_as_uint(ash[r0 * XP2 + k8 + tg + 4]);
            cah[3] = __float_as_uint(ash[(r0 + 8) * XP2 + k8 + tg + 4]);
            cal[0] = __float_as_uint(asl[r0 * XP2 + k8 + tg]);
            cal[1] = __float_as_uint(asl[(r0 + 8) * XP2 + k8 + tg]);
            cal[2] = __float_as_uint(asl[r0 * XP2 + k8 + tg + 4]);
            cal[3] = __float_as_uint(asl[(r0 + 8) * XP2 + k8 + tg + 4]);
            // A fragments: x operand (dt cols; wn==1 only)
            uint32_t xah[4], xal[4];
            if (wn) {
                xah[0] = __float_as_uint(xsh[r0 * XP2 + k8 + tg]);
                xah[1] = __float_as_uint(xsh[(r0 + 8) * XP2 + k8 + tg]);
                xah[2] = __float_as_uint(xsh[r0 * XP2 + k8 + tg + 4]);
                xah[3] = __float_as_uint(xsh[(r0 + 8) * XP2 + k8 + tg + 4]);
                xal[0] = __float_as_uint(xsl[r0 * XP2 + k8 + tg]);
                xal[1] = __float_as_uint(xsl[(r0 + 8) * XP2 + k8 + tg]);
                xal[2] = __float_as_uint(xsl[r0 * XP2 + k8 + tg + 4]);
                xal[3] = __float_as_uint(xsl[(r0 + 8) * XP2 + k8 + tg + 4]);
            }
            // B fragments
            uint32_t bh[5][2], bl[5][2];
#pragma unroll
            for (int nf = 0; nf < 5; nf++) {
                int c0 = 40 * wn + 8 * nf + g;
                bh[nf][0] = __float_as_uint(wbh[c0 * XP2 + k8 + tg]);
                bh[nf][1] = __float_as_uint(wbh[c0 * XP2 + k8 + tg + 4]);
                bl[nf][0] = __float_as_uint(wbl[c0 * XP2 + k8 + tg]);
                bl[nf][1] = __float_as_uint(wbl[c0 * XP2 + k8 + tg + 4]);
            }
            // MMAs
            if (wn == 0) {
                MMA3(acc[0], cah, cal, bh[0], bl[0]);
                MMA3(acc[1], cah, cal, bh[1], bl[1]);
                MMA3(acc[2], cah, cal, bh[2], bl[2]);
                MMA3(acc[3], cah, cal, bh[3], bl[3]);
                MMA3(acc[4], cah, cal, bh[4], bl[4]);
            } else {
                MMA3(acc[0], cah, cal, bh[0], bl[0]);
                MMA3(acc[1], cah, cal, bh[1], bl[1]);
                MMA3(acc[2], cah, cal, bh[2], bl[2]);
                MMA3(acc[3], xah, xal, bh[3], bl[3]);
                MMA3(acc[4], xah, xal, bh[4], bl[4]);
            }
        }
        __syncthreads();
    }

    // ---- write partials to g_mid[kc][c][row] ----
    // fragment: thread (g,tg) holds D[g][2tg], D[g][2tg+1], D[g+8][2tg], D[g+8][2tg+1]
    {
        float* mid = g_mid + (size_t)blockIdx.x * 80 * BT;
        size_t r0 = (size_t)base + 16 * wm + g;
#pragma unroll
        for (int nf = 0; nf < 5; nf++) {
            int c = 40 * wn + 8 * nf + 2 * tg;
            float4 v = acc[nf];
            mid[(size_t)c * BT + r0] = v.x;
            mid[(size_t)(c + 1) * BT + r0] = v.y;
            mid[(size_t)c * BT + r0 + 8] = v.z;
            mid[(size_t)(c + 1) * BT + r0 + 8] = v.w;
        }
    }
}

// ---------------------------------------------------------------------------
// Stage 1b: reduce partials, biases, tanh, tr_w GEMM; write interleaved g_dp.
// grid 256, block 256. g_mid is [kc][c][row]. (verified round 8)
// ---------------------------------------------------------------------------
__global__ __launch_bounds__(256) void stage1b_kernel(
    const float* __restrict__ in_b,
    const float* __restrict__ dt_b,
    const float* __restrict__ tr_w)
{
    __shared__ float sdm[64 * 16];
    __shared__ float str[16 * 64];
    __shared__ float sproj[64 * 68];   // [r][c], pitch 68

    const int tid = threadIdx.x;
    const int base = blockIdx.x * 64;
    const int cg = tid & 15;
    const int rg = tid >> 4;

    for (int idx = tid; idx < NN * RR; idx += 256) {
        int n = idx >> 4, r = idx & 15;
        str[r * 64 + n] = tr_w[idx];
    }

    float dtb = dt_b[cg];
#pragma unroll
    for (int i = 0; i < 4; i++) {
        size_t row = base + 4 * rg + i;
#pragma unroll
        for (int m = 0; m < 4; m++) {
            int c = cg + 16 * m;
            float v = in_b[c];
#pragma unroll
            for (int kc = 0; kc < 4; kc++)
                v += g_mid[((size_t)kc * 80 + c) * BT + row];
            sproj[(4 * rg + i) * 68 + c] = v;
        }
        float dm = dtb;
#pragma unroll
        for (int kc = 0; kc < 4; kc++)
            dm += g_mid[((size_t)kc * 80 + 64 + cg) * BT + row];
        sdm[(4 * rg + i) * 16 + cg] = tanhf(dm);
    }
    __syncthreads();

    float a2[4][4];
#pragma unroll
    for (int i = 0; i < 4; i++)
#pragma unroll
        for (int j = 0; j < 4; j++) a2[i][j] = 0.f;
#pragma unroll
    for (int r = 0; r < 16; r++) {
        float d0 = sdm[(4 * rg + 0) * 16 + r];
        float d1 = sdm[(4 * rg + 1) * 16 + r];
        float d2 = sdm[(4 * rg + 2) * 16 + r];
        float d3 = sdm[(4 * rg + 3) * 16 + r];
        float w0 = str[r * 64 + 4 * cg + 0];
        float w1 = str[r * 64 + 4 * cg + 1];
        float w2 = str[r * 64 + 4 * cg + 2];
        float w3 = str[r * 64 + 4 * cg + 3];
        a2[0][0] = fmaf(d0, w0, a2[0][0]); a2[0][1] = fmaf(d0, w1, a2[0][1]);
        a2[0][2] = fmaf(d0, w2, a2[0][2]); a2[0][3] = fmaf(d0, w3, a2[0][3]);
        a2[1][0] = fmaf(d1, w0, a2[1][0]); a2[1][1] = fmaf(d1, w1, a2[1][1]);
        a2[1][2] = fmaf(d1, w2, a2[1][2]); a2[1][3] = fmaf(d1, w3, a2[1][3]);
        a2[2][0] = fmaf(d2, w0, a2[2][0]); a2[2][1] = fmaf(d2, w1, a2[2][1]);
        a2[2][2] = fmaf(d2, w2, a2[2][2]); a2[2][3] = fmaf(d2, w3, a2[2][3]);
        a2[3][0] = fmaf(d3, w0, a2[3][0]); a2[3][1] = fmaf(d3, w1, a2[3][1]);
        a2[3][2] = fmaf(d3, w2, a2[3][2]); a2[3][3] = fmaf(d3, w3, a2[3][3]);
    }
#pragma unroll
    for (int i = 0; i < 4; i++) {
        size_t row = base + 4 * rg + i;
        const float* pr = sproj + (4 * rg + i) * 68 + 4 * cg;
        float4 v0 = make_float4(a2[i][0], pr[0], a2[i][1], pr[1]);
        float4 v1 = make_float4(a2[i][2], pr[2], a2[i][3], pr[3]);
        float* dst = (float*)(g_dp + row * NN + 4 * cg);
        *(float4*)(dst) = v0;
        *(float4*)(dst + 4) = v1;
    }
}

// ---------------------------------------------------------------------------
// Stage 2: sequential scan, 256 chains, 20-cycle chain.
// Iterate on h = y/2: h' = fmaf(0.5h, tanh(h), c), c = 0.5h + 0.5p + 0.5d_next
// (0.5h and c resolve during the MUFU). Store s = fmaf(h, th, h + p) off-chain.
// ---------------------------------------------------------------------------
__device__ __forceinline__ float fast_tanh(float v) {
    float r;
    asm("tanh.approx.f32 %0, %1;" : "=f"(r) : "f"(v));
    return r;
}

__global__ __launch_bounds__(32) void scan_kernel()
{
    const int chain = blockIdx.x * 32 + threadIdx.x;   // 8 blocks x 32 threads
    const int b = chain >> 6;
    const int n = chain & 63;
    const float2* pdp = g_dp + (size_t)b * TT * NN + n;
    float* ps = g_states + (size_t)b * TT * NN + n;

    float2 dpA[SG];   // raw {d, p}
#pragma unroll
    for (int i = 0; i < SG; i++) dpA[i] = pdp[i * NN];

    float h = 0.5f * dpA[0].x;   // h_0 = 0.5*(s_init + d_0), s_init = 0

    for (int t0 = 0; t0 < TT; t0 += SG) {
        float2 dpB[SG];
        int tn = t0 + SG;
        // padded tail: reads past TT land in the pad region, values unused
#pragma unroll
        for (int i = 0; i < SG; i++) dpB[i] = pdp[(tn + i) * NN];
#pragma unroll
        for (int i = 0; i < SG; i++) {
            float p = dpA[i].y;
            float dnext = (i < SG - 1) ? dpA[i + 1].x : dpB[0].x;
            float th = fast_tanh(h);                   // chain +16
            float h05 = 0.5f * h;                      // off-chain
            float c = fmaf(0.5f, dnext, fmaf(0.5f, p, h05));  // off-chain
            float hp = h + p;                          // off-chain
            ps[(t0 + i) * NN] = fmaf(h, th, hp);       // s_t, off-chain
            h = fmaf(h05, th, c);                      // chain +4  => 20 cyc
        }
#pragma unroll
        for (int i = 0; i < SG; i++) dpA[i] = dpB[i];
    }
}

// ---------------------------------------------------------------------------
// Stage 3: out = states @ out_w^T + out_b via split-tf32 mma.sync.
// Block 128(M) x 64(N), 8 warps, warp tile 32x32 (2 m16 x 4 n8), K=64.
// (verified round 8, 50.6 us)
// ---------------------------------------------------------------------------
#define S3PAD 68

__global__ __launch_bounds__(256) void stage3_kernel(
    const float* __restrict__ out_w,
    const float* __restrict__ out_b,
    float* __restrict__ out)
{
    extern __shared__ float smem3[];
    float* sA = smem3;                 // [128][S3PAD]
    float* sB = smem3 + 128 * S3PAD;   // [64][S3PAD]

    const int tid = threadIdx.x;
    const int rbase = blockIdx.y * 128;
    const int cbase = blockIdx.x * 64;
    const int warp = tid >> 5;
    const int lane = tid & 31;
    const int wm = warp >> 1;
    const int wn = warp & 1;
    const int g = lane >> 2;
    const int tg = lane & 3;

    for (int idx = tid; idx < 128 * 16; idx += 256) {
        int r = idx >> 4, q = idx & 15;
        float4 v = *(const float4*)(g_states + (size_t)(rbase + r) * NN + 4 * q);
        *(float4*)(sA + r * S3PAD + 4 * q) = v;
    }
    for (int idx = tid; idx < 64 * 16; idx += 256) {
        int c = idx >> 4, q = idx & 15;
        float4 v = *(const float4*)(out_w + (size_t)(cbase + c) * NN + 4 * q);
        *(float4*)(sB + c * S3PAD + 4 * q) = v;
    }
    __syncthreads();

    float4 acc[2][4];
#pragma unroll
    for (int i = 0; i < 2; i++)
#pragma unroll
        for (int j = 0; j < 4; j++) acc[i][j] = make_float4(0.f, 0.f, 0.f, 0.f);

#pragma unroll
    for (int k0 = 0; k0 < 64; k0 += 8) {
        uint32_t ahi[2][4], alo[2][4];
#pragma unroll
        for (int mf = 0; mf < 2; mf++) {
            int r0 = wm * 32 + mf * 16 + g;
            float av[4];
            av[0] = sA[r0 * S3PAD + k0 + tg];
            av[1] = sA[(r0 + 8) * S3PAD + k0 + tg];
            av[2] = sA[r0 * S3PAD + k0 + tg + 4];
            av[3] = sA[(r0 + 8) * S3PAD + k0 + tg + 4];
#pragma unroll
            for (int q = 0; q < 4; q++) {
                uint32_t h = tf32_hi(av[q]);
                ahi[mf][q] = h;
                alo[mf][q] = tf32_hi(av[q] - __uint_as_float(h));
            }
        }
        uint32_t bhi[4][2], blo[4][2];
#pragma unroll
        for (int nf = 0; nf < 4; nf++) {
            int c0 = wn * 32 + nf * 8 + g;
            float bv[2];
            bv[0] = sB[c0 * S3PAD + k0 + tg];
            bv[1] = sB[c0 * S3PAD + k0 + tg + 4];
#pragma unroll
            for (int q = 0; q < 2; q++) {
                uint32_t h = tf32_hi(bv[q]);
                bhi[nf][q] = h;
                blo[nf][q] = tf32_hi(bv[q] - __uint_as_float(h));
            }
        }
#pragma unroll
        for (int mf = 0; mf < 2; mf++) {
#pragma unroll
            for (int nf = 0; nf < 4; nf++) {
                MMA3(acc[mf][nf], ahi[mf], alo[mf], bhi[nf], blo[nf]);
            }
        }
    }

#pragma unroll
    for (int nf = 0; nf < 4; nf++) {
        int c = cbase + wn * 32 + nf * 8 + 2 * tg;
        float b0 = out_b[c], b1 = out_b[c + 1];
#pragma unroll
        for (int mf = 0; mf < 2; mf++) {
            int r0 = rbase + wm * 32 + mf * 16 + g;
            float4 v = acc[mf][nf];
            *(float2*)(out + (size_t)r0 * DD + c) = make_float2(v.x + b0, v.y + b1);
            *(float2*)(out + (size_t)(r0 + 8) * DD + c) = make_float2(v.z + b0, v.w + b1);
        }
    }
}

// ---------------------------------------------------------------------------
extern "C" void kernel_launch(void* const* d_in, const int* in_sizes, int n_in,
                              void* d_out, int out_size)
{
    const float* x      = (const float*)d_in[0];
    const float* conv_w = (const float*)d_in[1];
    const float* in_w   = (const float*)d_in[2];
    const float* in_b   = (const float*)d_in[3];
    const float* dt_w   = (const float*)d_in[4];
    const float* dt_b   = (const float*)d_in[5];
    const float* tr_w   = (const float*)d_in[6];
    const float* out_w  = (const float*)d_in[7];
    const float* out_b  = (const float*)d_in[8];
    float* out = (float*)d_out;

    const int s1_smem = (NROW * XP2 + 4 * 64 * XP2 + 2 * 80 * XP2 + 128)
                        * sizeof(float);   // 70064 B
    cudaFuncSetAttribute(stage1a_kernel,
                         cudaFuncAttributeMaxDynamicSharedMemorySize, s1_smem);
    const int s3_smem = (128 + 64) * S3PAD * sizeof(float);  // 52224 B
    cudaFuncSetAttribute(stage3_kernel,
                         cudaFuncAttributeMaxDynamicSharedMemorySize, s3_smem);

    prep_w_kernel<<<320, 256>>>(in_w, dt_w);
    stage1a_kernel<<<dim3(4, 256), 256, s1_smem>>>(x, conv_w);
    stage1b_kernel<<<256, 256>>>(in_b, dt_b, tr_w);
    scan_kernel<<<8, 32>>>();
    stage3_kernel<<<dim3(16, 128), 256, s3_smem>>>(out_w, out_b, out);
}